// round 14
// baseline (speedup 1.0000x reference)
#include <cuda_runtime.h>
#include <cstdint>

#define FULLMASK 0xffffffffu
#define MM 3
#define BB 64
#define DD 512
#define DQ 128
#define L2E 1.4426950408889634f
#define INV_SCALE 0.044194173824159216f   /* 1/sqrt(512) */
#define NSPL 8
#define K1_BLOCKS (8 * NSPL * MM)   /* 192; 2-per-SM co-resident */
#define K4_BLOCKS (128 * MM)        /* 384; 3-per-SM via launch_bounds */

typedef unsigned long long u64t;

#define PK2(out, lo, hi)  asm("mov.b64 %0, {%1, %2};" : "=l"(out) : "f"(lo), "f"(hi))
#define UPK2(lo, hi, in)  asm("mov.b64 {%0, %1}, %2;" : "=f"(lo), "=f"(hi) : "l"(in))
#define MUL2(out, a, b)   asm("mul.rn.f32x2 %0, %1, %2;" : "=l"(out) : "l"(a), "l"(b))
#define ADD2(out, a, b)   asm("add.rn.f32x2 %0, %1, %2;" : "=l"(out) : "l"(a), "l"(b))
#define FMA2(out, a, b, c) asm("fma.rn.f32x2 %0, %1, %2, %3;" : "=l"(out) : "l"(a), "l"(b), "l"(c))

// ---------------- scratch ----------------
__device__ float g_Y4[NSPL * MM * BB * DD];
__device__ float g_P [MM * BB * DD];
__device__ float g_HA[MM * BB * DQ];
__device__ float g_WF[MM * BB * DD];
__device__ float g_WFT[MM * DD * BB];
__device__ float g_S [MM * BB];
__device__ float g_A1[MM * BB * DD];
__device__ float g_A2[MM * BB * DD];
__device__ unsigned g_bar1;
__device__ unsigned g_bar2;

__device__ __forceinline__ float ex2f_(float x) {
    float r; asm("ex2.approx.ftz.f32 %0, %1;" : "=f"(r) : "f"(x)); return r;
}
__device__ __forceinline__ float frcp_(float x) {
    float r; asm("rcp.approx.ftz.f32 %0, %1;" : "=f"(r) : "f"(x)); return r;
}
__device__ __forceinline__ float sigm_(float x) {
    return frcp_(1.0f + ex2f_(-x * L2E));
}

// ================= K1: gemm1 (split-K 8, software-pipelined) + grid barrier + LN/ReLU =================
__global__ __launch_bounds__(256, 2) void k1_gemm1_ln(
    const float* __restrict__ X, const float* __restrict__ W,
    const float* __restrict__ pb, const float* __restrict__ lg,
    const float* __restrict__ lb)
{
    __shared__ float As[16][64];
    __shared__ float Bs[16][64];
    __shared__ float red[18];

    const int i  = blockIdx.z;
    const int n0 = blockIdx.x * 64;
    const int k0 = blockIdx.y * 64;
    const int tid = threadIdx.x;
    const int tx = tid & 15, ty = tid >> 4;

    const float* Xb = X + (size_t)i * BB * DD;
    const float* Wb = W + (size_t)i * DD * DD;

    const int r  = tid >> 2;
    const int c4 = (tid & 3) * 4;

    // prologue: load chunk 0 into registers
    float4 xa = *(const float4*)&Xb[(size_t)r * DD + k0 + c4];
    float4 wa = *(const float4*)&Wb[(size_t)(n0 + r) * DD + k0 + c4];

    float acc[4][4] = {};
    #pragma unroll
    for (int kk = 0; kk < 64; kk += 16) {
        // stage current chunk from registers
        As[c4+0][r] = xa.x; As[c4+1][r] = xa.y; As[c4+2][r] = xa.z; As[c4+3][r] = xa.w;
        Bs[c4+0][r] = wa.x; Bs[c4+1][r] = wa.y; Bs[c4+2][r] = wa.z; Bs[c4+3][r] = wa.w;
        __syncthreads();
        // prefetch next chunk (overlaps the FMA loop below)
        if (kk < 48) {
            xa = *(const float4*)&Xb[(size_t)r * DD + k0 + kk + 16 + c4];
            wa = *(const float4*)&Wb[(size_t)(n0 + r) * DD + k0 + kk + 16 + c4];
        }
        #pragma unroll
        for (int p = 0; p < 16; ++p) {
            float4 a4 = *(const float4*)&As[p][ty * 4];
            float4 b4 = *(const float4*)&Bs[p][tx * 4];
            float av[4] = {a4.x, a4.y, a4.z, a4.w};
            float bv[4] = {b4.x, b4.y, b4.z, b4.w};
            #pragma unroll
            for (int m2 = 0; m2 < 4; ++m2)
                #pragma unroll
                for (int n2 = 0; n2 < 4; ++n2)
                    acc[m2][n2] = fmaf(av[m2], bv[n2], acc[m2][n2]);
        }
        __syncthreads();
    }
    {
        float* Cout = g_Y4 + (size_t)blockIdx.y * (MM * BB * DD) + (size_t)i * BB * DD;
        #pragma unroll
        for (int m2 = 0; m2 < 4; ++m2) {
            int b = ty * 4 + m2;
            float4 v = make_float4(acc[m2][0], acc[m2][1], acc[m2][2], acc[m2][3]);
            *(float4*)&Cout[(size_t)b * DD + n0 + tx * 4] = v;
        }
    }

    __threadfence();
    __syncthreads();
    if (tid == 0) {
        unsigned old = atomicAdd(&g_bar1, 1u);
        unsigned target = (old / K1_BLOCKS + 1u) * K1_BLOCKS;
        while ((int)(*(volatile unsigned*)&g_bar1 - target) < 0) {
            __nanosleep(32);
        }
    }
    __syncthreads();

    const int flat = (blockIdx.z * NSPL + blockIdx.y) * 8 + blockIdx.x;  // 0..191
    const int warp = tid >> 5, lane = tid & 31;
    if (flat == 0 && tid < MM * BB) g_S[tid] = 0.0f;

    const int row = flat;
    const int i2  = row >> 6;
    const size_t base = (size_t)row * DD;
    const int e0 = tid, e1 = tid + 256;

    float y0 = pb[i2 * DD + e0];
    float y1 = pb[i2 * DD + e1];
    #pragma unroll
    for (int s = 0; s < NSPL; ++s) {
        y0 += g_Y4[(size_t)s * MM * BB * DD + base + e0];
        y1 += g_Y4[(size_t)s * MM * BB * DD + base + e1];
    }
    float s = y0 + y1, q = y0 * y0 + y1 * y1;
    #pragma unroll
    for (int off = 16; off; off >>= 1) {
        s += __shfl_xor_sync(FULLMASK, s, off);
        q += __shfl_xor_sync(FULLMASK, q, off);
    }
    if (lane == 0) { red[warp] = s; red[8 + warp] = q; }
    __syncthreads();
    if (warp == 0) {
        float s2 = red[lane & 7], q2 = red[8 + (lane & 7)];
        #pragma unroll
        for (int off = 4; off; off >>= 1) {
            s2 += __shfl_xor_sync(FULLMASK, s2, off);
            q2 += __shfl_xor_sync(FULLMASK, q2, off);
        }
        if (lane == 0) { red[16] = s2; red[17] = q2; }
    }
    __syncthreads();
    float mu  = red[16] * (1.0f / DD);
    float var = red[17] * (1.0f / DD) - mu * mu;
    float rs  = rsqrtf(var + 1e-5f);
    float p0 = (y0 - mu) * rs * lg[i2 * DD + e0] + lb[i2 * DD + e0];
    float p1 = (y1 - mu) * rs * lg[i2 * DD + e1] + lb[i2 * DD + e1];
    g_P[base + e0] = fmaxf(p0, 0.0f);
    g_P[base + e1] = fmaxf(p1, 0.0f);
}

// ================= K2: HA = relu(P @ W1^T + b1) =================
__global__ void gemm_hidden_kernel(const float* __restrict__ W1, const float* __restrict__ b1)
{
    const int i  = blockIdx.y;
    const int b0 = (blockIdx.x & 7) * 8;
    const int n0 = (blockIdx.x >> 3) * 64;
    const int tid = threadIdx.x;
    const int tx = tid & 15, ty = tid >> 4;

    __shared__ __align__(16) float As[32][8];
    __shared__ __align__(16) float Bs[32][64];

    const float* Pb = g_P + (size_t)i * BB * DD;
    const float* Wb = W1 + (size_t)i * DQ * DD;

    float acc[4] = {};
    for (int k0 = 0; k0 < DD; k0 += 32) {
        if (tid < 64) {
            int r = tid >> 3, q = tid & 7;
            float4 v = *(const float4*)&Pb[(size_t)(b0 + r) * DD + k0 + q * 4];
            As[q*4+0][r] = v.x; As[q*4+1][r] = v.y; As[q*4+2][r] = v.z; As[q*4+3][r] = v.w;
        }
        #pragma unroll
        for (int q = 0; q < 4; ++q) {
            int idx = tid * 4 + q;
            int nr = idx >> 3, kq = idx & 7;
            float4 v = *(const float4*)&Wb[(size_t)(n0 + nr) * DD + k0 + kq * 4];
            Bs[kq*4+0][nr] = v.x; Bs[kq*4+1][nr] = v.y; Bs[kq*4+2][nr] = v.z; Bs[kq*4+3][nr] = v.w;
        }
        __syncthreads();
        #pragma unroll
        for (int k = 0; k < 32; ++k) {
            float a = As[k][ty];
            float4 w4 = *(const float4*)&Bs[k][tx * 4];
            acc[0] = fmaf(a, w4.x, acc[0]);
            acc[1] = fmaf(a, w4.y, acc[1]);
            acc[2] = fmaf(a, w4.z, acc[2]);
            acc[3] = fmaf(a, w4.w, acc[3]);
        }
        __syncthreads();
    }
    float4 o;
    o.x = fmaxf(acc[0] + b1[i*DQ + n0 + tx*4 + 0], 0.0f);
    o.y = fmaxf(acc[1] + b1[i*DQ + n0 + tx*4 + 1], 0.0f);
    o.z = fmaxf(acc[2] + b1[i*DQ + n0 + tx*4 + 2], 0.0f);
    o.w = fmaxf(acc[3] + b1[i*DQ + n0 + tx*4 + 3], 0.0f);
    *(float4*)&g_HA[((size_t)i * BB + b0 + ty) * DQ + n0 + tx * 4] = o;
}

// ================= K3: CW = HA @ W2^T + fused wf epilogue =================
__global__ void gemm_cw_wf_kernel(const float* __restrict__ W2,
                                  const float* __restrict__ b2v)
{
    const int i  = blockIdx.y;
    const int n0 = blockIdx.x * 32;
    const int tid = threadIdx.x;
    const int tx = tid & 7, ty = tid >> 3;

    __shared__ __align__(16) float As2[64][DQ];
    __shared__ __align__(16) float Bs[DQ][36];

    #pragma unroll
    for (int q = 0; q < 8; ++q) {
        int idx = tid + q * 256;
        int b = idx >> 5, kq = idx & 31;
        float4 v = *(const float4*)&g_HA[((size_t)i * BB + b) * DQ + kq * 4];
        *(float4*)&As2[b][kq * 4] = v;
    }
    #pragma unroll
    for (int q = 0; q < 4; ++q) {
        int idx = tid + q * 256;
        int nr = idx >> 5, kq = idx & 31;
        float4 v = *(const float4*)&W2[((size_t)i * DD + n0 + nr) * DQ + kq * 4];
        Bs[kq*4+0][nr] = v.x; Bs[kq*4+1][nr] = v.y; Bs[kq*4+2][nr] = v.z; Bs[kq*4+3][nr] = v.w;
    }
    __syncthreads();

    float acc[2][4] = {};
    #pragma unroll 8
    for (int k4 = 0; k4 < 32; ++k4) {
        float4 a0 = *(const float4*)&As2[ty][k4 * 4];
        float4 a1 = *(const float4*)&As2[ty + 32][k4 * 4];
        float av0[4] = {a0.x, a0.y, a0.z, a0.w};
        float av1[4] = {a1.x, a1.y, a1.z, a1.w};
        #pragma unroll
        for (int q = 0; q < 4; ++q) {
            float4 b4 = *(const float4*)&Bs[k4 * 4 + q][tx * 4];
            float bv[4] = {b4.x, b4.y, b4.z, b4.w};
            #pragma unroll
            for (int n2 = 0; n2 < 4; ++n2) {
                acc[0][n2] = fmaf(av0[q], bv[n2], acc[0][n2]);
                acc[1][n2] = fmaf(av1[q], bv[n2], acc[1][n2]);
            }
        }
    }

    #pragma unroll
    for (int rr = 0; rr < 2; ++rr) {
        int b = ty + rr * 32;
        int n = n0 + tx * 4;
        float4 p4 = *(const float4*)&g_P[((size_t)i * BB + b) * DD + n];
        float pv[4] = {p4.x, p4.y, p4.z, p4.w};
        float w[4], srow = 0.0f;
        #pragma unroll
        for (int q = 0; q < 4; ++q) {
            float pre = acc[rr][q] + b2v[i * DD + n + q];
            w[q] = pv[q] * sigm_(pre);
            srow += w[q];
            g_WFT[((size_t)i * DD + n + q) * BB + b] = w[q];
        }
        *(float4*)&g_WF[((size_t)i * BB + b) * DD + n] = make_float4(w[0], w[1], w[2], w[3]);
        #pragma unroll
        for (int off = 4; off; off >>= 1)
            srow += __shfl_xor_sync(FULLMASK, srow, off);
        if (tx == 0) atomicAdd(&g_S[i * BB + b], srow);
    }
}

// ================= K4: merged pairwise attention + combine (R10 structure) =================

template<int PASS>
__device__ __forceinline__ void run_pass(float4 (*sv)[8][128],
                                         float (*pw)[36],
                                         int j, int d, int lane, int warp, int bhalf,
                                         float a0, u64t (&hrp)[8],
                                         float cL, float isc, float g, float mb,
                                         float* __restrict__ accout)
{
    const int tid = warp * 32 + lane;
    const int bs = bhalf * 32;
    const float* wfj = g_WF + (size_t)j * BB * DD;
    const float isc8 = isc * 0.8f, isc2 = isc * 0.2f, cL8 = cL * 0.8f;

    u64t k02p, k08p, hnp[8];
    if (PASS == 1) {
        PK2(k02p, 0.2f, 0.2f);
        PK2(k08p, 0.8f, 0.8f);
        u64t kn1; PK2(kn1, -1.0f, -1.0f);
        #pragma unroll
        for (int q = 0; q < 8; ++q) MUL2(hnp[q], hrp[q], kn1);
    }

    #pragma unroll
    for (int q = 0; q < 4; ++q) {
        int idx = tid + q * 256;
        int rl = idx >> 7, col = idx & 127;
        int grow = (rl >> 2) * 32 + (rl & 3);
        sv[0][rl][col] = *(const float4*)&wfj[(size_t)grow * DD + col * 4];
    }
    __syncthreads();

    for (int c = 0; c < 8; ++c) {
        const int buf = c & 1;
        float4 nx[4];
        if (c < 7) {
            #pragma unroll
            for (int q = 0; q < 4; ++q) {
                int idx = tid + q * 256;
                int rl = idx >> 7, col = idx & 127;
                int grow = (rl >> 2) * 32 + (c + 1) * 4 + (rl & 3);
                nx[q] = *(const float4*)&wfj[(size_t)grow * DD + col * 4];
            }
        }
        #pragma unroll
        for (int bi = 0; bi < 4; ++bi) {
            const int bl = c * 4 + bi;
            float a  = __shfl_sync(FULLMASK, a0, bl);

            u64t sep, dotp;
            { float z = 0.0f; PK2(sep, z, z); PK2(dotp, z, z); }
            const float4* vr = sv[buf][bhalf * 4 + bi];

            if (PASS == 0) {
                u64t ap8p, ap2p;
                { float a8 = a * isc8, a2 = a * isc2; PK2(ap8p, a8, a8); PK2(ap2p, a2, a2); }
                #pragma unroll
                for (int k = 0; k < 4; ++k) {
                    float4 v = vr[k * 32 + lane];
                    u64t vp[2]; PK2(vp[0], v.x, v.y); PK2(vp[1], v.z, v.w);
                    #pragma unroll
                    for (int h2 = 0; h2 < 2; ++h2) {
                        u64t cur; MUL2(cur, ap8p, vp[h2]);
                        float c0, c1; UPK2(c0, c1, cur);
                        float m0 = fminf(fmaxf(c0, -cL8), cL8);
                        float m1 = fminf(fmaxf(c1, -cL8), cL8);
                        u64t mp; PK2(mp, m0, m1);
                        u64t f; FMA2(f, ap2p, vp[h2], mp);
                        ADD2(hrp[k*2+h2], hrp[k*2+h2], f);
                        float f0, f1; UPK2(f0, f1, f);
                        float e0 = ex2f_(f0), e1 = ex2f_(f1);
                        u64t ep; PK2(ep, e0, e1);
                        ADD2(sep, sep, ep);
                        FMA2(dotp, ep, vp[h2], dotp);
                    }
                }
            } else {
                u64t app;
                { float av = a * isc; PK2(app, av, av); }
                #pragma unroll
                for (int k = 0; k < 4; ++k) {
                    float4 v = vr[k * 32 + lane];
                    u64t vp[2]; PK2(vp[0], v.x, v.y); PK2(vp[1], v.z, v.w);
                    #pragma unroll
                    for (int h2 = 0; h2 < 2; ++h2) {
                        u64t u_; FMA2(u_, app, vp[h2], hnp[k*2+h2]);
                        float u0, u1; UPK2(u0, u1, u_);
                        float m0 = fminf(fmaxf(u0, -cL), cL);
                        float m1 = fminf(fmaxf(u1, -cL), cL);
                        u64t mp; PK2(mp, m0, m1);
                        u64t t; FMA2(t, k02p, u_, hrp[k*2+h2]);
                        u64t f; FMA2(f, k08p, mp, t);
                        float f0, f1; UPK2(f0, f1, f);
                        float e0 = ex2f_(f0), e1 = ex2f_(f1);
                        u64t ep; PK2(ep, e0, e1);
                        ADD2(sep, sep, ep);
                        FMA2(dotp, ep, vp[h2], dotp);
                    }
                }
            }
            float sl, sh, dl, dh;
            UPK2(sl, sh, sep); UPK2(dl, dh, dotp);
            pw[bi * 2 + 0][lane] = sl + sh;
            pw[bi * 2 + 1][lane] = dl + dh;
        }
        __syncwarp();
        if (lane < 8) {
            const float4* pr = (const float4*)pw[lane];
            float4 p0 = pr[0], p1 = pr[1], p2 = pr[2], p3 = pr[3];
            float4 p4 = pr[4], p5 = pr[5], p6 = pr[6], p7 = pr[7];
            p0.x += p1.x; p0.y += p1.y; p0.z += p1.z; p0.w += p1.w;
            p2.x += p3.x; p2.y += p3.y; p2.z += p3.z; p2.w += p3.w;
            p4.x += p5.x; p4.y += p5.y; p4.z += p5.z; p4.w += p5.w;
            p6.x += p7.x; p6.y += p7.y; p6.z += p7.z; p6.w += p7.w;
            p0.x += p2.x; p0.y += p2.y; p0.z += p2.z; p0.w += p2.w;
            p4.x += p6.x; p4.y += p6.y; p4.z += p6.z; p4.w += p6.w;
            float val = (p0.x + p4.x) + (p0.y + p4.y) + (p0.z + p4.z) + (p0.w + p4.w);
            float sev = __shfl_sync(0xFFu, val, lane & ~1);
            if (lane & 1) {
                int bl = c * 4 + (lane >> 1);
                float sj = __ldg(&g_S[j * BB + bs + bl]);
                accout[(size_t)(bs + bl) * DD + d] = g * (val * frcp_(sev) + mb * sj);
            }
        }
        if (c < 7) {
            #pragma unroll
            for (int q = 0; q < 4; ++q) {
                int idx = tid + q * 256;
                int rl = idx >> 7, col = idx & 127;
                sv[buf ^ 1][rl][col] = nx[q];
            }
        }
        __syncthreads();
    }
}

__global__ __launch_bounds__(256, 3) void attn_combine_kernel(
    const float* __restrict__ gamma,
    const float* __restrict__ mbias,
    const float* __restrict__ constraint,
    float* __restrict__ out, int out_size)
{
    __shared__ __align__(16) float4 sv[2][8][128];      // 32 KB staging
    __shared__ __align__(16) float s_part[8][8][36];    // 9 KB partials
    const int i     = blockIdx.y;
    const int warp  = threadIdx.x >> 5;
    const int lane  = threadIdx.x & 31;
    const int bhalf = warp & 1;
    const int d     = blockIdx.x * 4 + (warp >> 1);
    const int tid   = threadIdx.x;
    const int j1 = (i == 0) ? 1 : 0;
    const int j2 = (i == 2) ? 1 : 2;

    const float cL  = constraint[i] * L2E;
    const float isc = INV_SCALE * L2E;
    const float a0 = __ldg(&g_WFT[((size_t)i * DD + d) * BB + bhalf * 32 + lane]);

    u64t hrp[8];
    { float z = 0.0f; u64t zp; PK2(zp, z, z);
      #pragma unroll
      for (int q = 0; q < 8; ++q) hrp[q] = zp; }

    {
        const float g1 = sigm_(gamma[i * MM + j1]);
        const float m1 = mbias[i * MM + j1];
        run_pass<0>(sv, s_part[warp], j1, d, lane, warp, bhalf, a0, hrp, cL, isc, g1, m1,
                    g_A1 + (size_t)i * BB * DD);
    }

    // ---- exchange hr across the warp pair (reuse sv buffer) ----
    __syncthreads();
    u64t* hx = (u64t*)sv;
    #pragma unroll
    for (int k = 0; k < 4; ++k) {
        float4* dst = (float4*)&hx[warp * 256 + (k * 32 + lane) * 2];
        float h0, h1, h2, h3;
        UPK2(h0, h1, hrp[k*2+0]); UPK2(h2, h3, hrp[k*2+1]);
        *dst = make_float4(h0, h1, h2, h3);
    }
    __syncthreads();
    {
        const int p = warp ^ 1;
        u64t k320; PK2(k320, (1.0f/320.0f), (1.0f/320.0f));
        #pragma unroll
        for (int k = 0; k < 4; ++k) {
            float4 hp = *(const float4*)&hx[p * 256 + (k * 32 + lane) * 2];
            u64t hp0, hp1; PK2(hp0, hp.x, hp.y); PK2(hp1, hp.z, hp.w);
            u64t s0, s1;
            ADD2(s0, hrp[k*2+0], hp0);
            ADD2(s1, hrp[k*2+1], hp1);
            MUL2(hrp[k*2+0], s0, k320);
            MUL2(hrp[k*2+1], s1, k320);
        }
    }
    __syncthreads();

    {
        const float g2 = sigm_(gamma[i * MM + j2]);
        const float m2 = mbias[i * MM + j2];
        run_pass<1>(sv, s_part[warp], j2, d, lane, warp, bhalf, a0, hrp, cL, isc, g2, m2,
                    g_A2 + (size_t)i * BB * DD);
    }

    // ---- grid barrier over all 384 blocks (3/SM co-resident by launch_bounds) ----
    __threadfence();
    __syncthreads();
    if (tid == 0) {
        unsigned old = atomicAdd(&g_bar2, 1u);
        unsigned target = (old / K4_BLOCKS + 1u) * K4_BLOCKS;
        while ((int)(*(volatile unsigned*)&g_bar2 - target) < 0) {
            __nanosleep(32);
        }
    }
    __syncthreads();

    // ---- combine phase: mode-0 blocks write the output ----
    if (i == 0) {
        const int idx = blockIdx.x * 256 + tid;   // 0..32767
        const int NBD = BB * DD;
        float w = (g_WF[idx] + g_WF[NBD + idx] + g_WF[2*NBD + idx]) * (1.0f / 3.0f);
        float a = g_A1[idx] + g_A1[NBD + idx] + g_A1[2*NBD + idx]
                + g_A2[idx] + g_A2[NBD + idx] + g_A2[2*NBD + idx];
        out[idx] = w + a * (1.0f / 6.0f);

        if (blockIdx.x == 0 && tid < MM && out_size >= NBD + MM) {
            float sc[MM];
            #pragma unroll
            for (int ii = 0; ii < MM; ++ii) {
                int ja = (ii == 0) ? 1 : 0;
                int jb = (ii == 2) ? 1 : 2;
                sc[ii] = 0.5f * (sigm_(gamma[ii * MM + ja]) + sigm_(gamma[ii * MM + jb]));
            }
            float mx = fmaxf(sc[0], fmaxf(sc[1], sc[2]));
            float e0 = ex2f_((sc[0] - mx) * L2E);
            float e1 = ex2f_((sc[1] - mx) * L2E);
            float e2 = ex2f_((sc[2] - mx) * L2E);
            float inv = frcp_(e0 + e1 + e2);
            float ei = (tid == 0) ? e0 : ((tid == 1) ? e1 : e2);
            out[NBD + tid] = ei * inv;
        }
    }
}

// ================= launch =================
extern "C" void kernel_launch(void* const* d_in, const int* in_sizes, int n_in,
                              void* d_out, int out_size)
{
    const float* x      = (const float*)d_in[0];
    const float* proj_W = (const float*)d_in[1];
    const float* proj_b = (const float*)d_in[2];
    const float* ln_g   = (const float*)d_in[3];
    const float* ln_b   = (const float*)d_in[4];
    const float* imp_W1 = (const float*)d_in[5];
    const float* imp_b1 = (const float*)d_in[6];
    const float* imp_W2 = (const float*)d_in[7];
    const float* imp_b2 = (const float*)d_in[8];
    const float* gamma  = (const float*)d_in[9];
    const float* mbias  = (const float*)d_in[10];
    const float* constr = (const float*)d_in[11];
    float* out = (float*)d_out;

    // 1) y = x @ proj_W^T (split-K 8, pipelined) + grid-sync + LN/ReLU
    k1_gemm1_ln<<<dim3(8, NSPL, MM), 256>>>(x, proj_W, proj_b, ln_g, ln_b);
    // 2) HA = relu(proj @ W1^T + b1)
    gemm_hidden_kernel<<<dim3(16, MM), 128>>>(imp_W1, imp_b1);
    // 3) CW = HA @ W2^T fused with wf epilogue
    gemm_cw_wf_kernel<<<dim3(16, MM), 256>>>(imp_W2, imp_b2);
    // 4) merged attention + grid barrier + combine (single wave, 3/SM)
    attn_combine_kernel<<<dim3(128, MM), 256>>>(gamma, mbias, constr, out, out_size);
}

// round 15
// speedup vs baseline: 1.0228x; 1.0228x over previous
#include <cuda_runtime.h>
#include <cstdint>

#define FULLMASK 0xffffffffu
#define MM 3
#define BB 64
#define DD 512
#define DQ 128
#define L2E 1.4426950408889634f
#define INV_SCALE 0.044194173824159216f   /* 1/sqrt(512) */
#define NSPL 8
#define K1_BLOCKS (8 * NSPL * MM)   /* 192; 2-per-SM co-resident */
#define K4_BLOCKS (128 * MM)        /* 384; 3-per-SM via launch_bounds */

typedef unsigned long long u64t;

#define PK2(out, lo, hi)  asm("mov.b64 %0, {%1, %2};" : "=l"(out) : "f"(lo), "f"(hi))
#define UPK2(lo, hi, in)  asm("mov.b64 {%0, %1}, %2;" : "=f"(lo), "=f"(hi) : "l"(in))
#define MUL2(out, a, b)   asm("mul.rn.f32x2 %0, %1, %2;" : "=l"(out) : "l"(a), "l"(b))
#define ADD2(out, a, b)   asm("add.rn.f32x2 %0, %1, %2;" : "=l"(out) : "l"(a), "l"(b))
#define FMA2(out, a, b, c) asm("fma.rn.f32x2 %0, %1, %2, %3;" : "=l"(out) : "l"(a), "l"(b), "l"(c))

// ---------------- scratch ----------------
__device__ float g_Y4[NSPL * MM * BB * DD];
__device__ float g_P [MM * BB * DD];
__device__ float g_HA[MM * BB * DQ];
__device__ float g_WF[MM * BB * DD];
__device__ float g_WFT[MM * DD * BB];
__device__ float g_S [MM * BB];
__device__ float g_A1[MM * BB * DD];
__device__ float g_A2[MM * BB * DD];
__device__ unsigned g_bar1;
__device__ unsigned g_bar2;

__device__ __forceinline__ float ex2f_(float x) {
    float r; asm("ex2.approx.ftz.f32 %0, %1;" : "=f"(r) : "f"(x)); return r;
}
__device__ __forceinline__ float frcp_(float x) {
    float r; asm("rcp.approx.ftz.f32 %0, %1;" : "=f"(r) : "f"(x)); return r;
}
__device__ __forceinline__ float sigm_(float x) {
    return frcp_(1.0f + ex2f_(-x * L2E));
}

// ================= K1: gemm1 (split-K 8) + grid barrier + LN/ReLU (R10 version) =================
__global__ __launch_bounds__(256, 2) void k1_gemm1_ln(
    const float* __restrict__ X, const float* __restrict__ W,
    const float* __restrict__ pb, const float* __restrict__ lg,
    const float* __restrict__ lb)
{
    __shared__ float As[16][64];
    __shared__ float Bs[16][64];
    __shared__ float red[18];

    const int i  = blockIdx.z;
    const int n0 = blockIdx.x * 64;
    const int k0 = blockIdx.y * 64;
    const int tid = threadIdx.x;
    const int tx = tid & 15, ty = tid >> 4;

    const float* Xb = X + (size_t)i * BB * DD;
    const float* Wb = W + (size_t)i * DD * DD;

    float acc[4][4] = {};
    for (int kk = 0; kk < 64; kk += 16) {
        {
            int r  = tid >> 2;
            int c4 = (tid & 3) * 4;
            float4 xa = *(const float4*)&Xb[(size_t)r * DD + k0 + kk + c4];
            As[c4+0][r] = xa.x; As[c4+1][r] = xa.y; As[c4+2][r] = xa.z; As[c4+3][r] = xa.w;
            float4 wa = *(const float4*)&Wb[(size_t)(n0 + r) * DD + k0 + kk + c4];
            Bs[c4+0][r] = wa.x; Bs[c4+1][r] = wa.y; Bs[c4+2][r] = wa.z; Bs[c4+3][r] = wa.w;
        }
        __syncthreads();
        #pragma unroll
        for (int p = 0; p < 16; ++p) {
            float4 a4 = *(const float4*)&As[p][ty * 4];
            float4 b4 = *(const float4*)&Bs[p][tx * 4];
            float av[4] = {a4.x, a4.y, a4.z, a4.w};
            float bv[4] = {b4.x, b4.y, b4.z, b4.w};
            #pragma unroll
            for (int m2 = 0; m2 < 4; ++m2)
                #pragma unroll
                for (int n2 = 0; n2 < 4; ++n2)
                    acc[m2][n2] = fmaf(av[m2], bv[n2], acc[m2][n2]);
        }
        __syncthreads();
    }
    {
        float* Cout = g_Y4 + (size_t)blockIdx.y * (MM * BB * DD) + (size_t)i * BB * DD;
        #pragma unroll
        for (int m2 = 0; m2 < 4; ++m2) {
            int b = ty * 4 + m2;
            float4 v = make_float4(acc[m2][0], acc[m2][1], acc[m2][2], acc[m2][3]);
            *(float4*)&Cout[(size_t)b * DD + n0 + tx * 4] = v;
        }
    }

    __threadfence();
    __syncthreads();
    if (tid == 0) {
        unsigned old = atomicAdd(&g_bar1, 1u);
        unsigned target = (old / K1_BLOCKS + 1u) * K1_BLOCKS;
        while ((int)(*(volatile unsigned*)&g_bar1 - target) < 0) {
            __nanosleep(32);
        }
    }
    __syncthreads();

    const int flat = (blockIdx.z * NSPL + blockIdx.y) * 8 + blockIdx.x;  // 0..191
    const int warp = tid >> 5, lane = tid & 31;
    if (flat == 0 && tid < MM * BB) g_S[tid] = 0.0f;

    const int row = flat;
    const int i2  = row >> 6;
    const size_t base = (size_t)row * DD;
    const int e0 = tid, e1 = tid + 256;

    float y0 = pb[i2 * DD + e0];
    float y1 = pb[i2 * DD + e1];
    #pragma unroll
    for (int s = 0; s < NSPL; ++s) {
        y0 += g_Y4[(size_t)s * MM * BB * DD + base + e0];
        y1 += g_Y4[(size_t)s * MM * BB * DD + base + e1];
    }
    float s = y0 + y1, q = y0 * y0 + y1 * y1;
    #pragma unroll
    for (int off = 16; off; off >>= 1) {
        s += __shfl_xor_sync(FULLMASK, s, off);
        q += __shfl_xor_sync(FULLMASK, q, off);
    }
    if (lane == 0) { red[warp] = s; red[8 + warp] = q; }
    __syncthreads();
    if (warp == 0) {
        float s2 = red[lane & 7], q2 = red[8 + (lane & 7)];
        #pragma unroll
        for (int off = 4; off; off >>= 1) {
            s2 += __shfl_xor_sync(FULLMASK, s2, off);
            q2 += __shfl_xor_sync(FULLMASK, q2, off);
        }
        if (lane == 0) { red[16] = s2; red[17] = q2; }
    }
    __syncthreads();
    float mu  = red[16] * (1.0f / DD);
    float var = red[17] * (1.0f / DD) - mu * mu;
    float rs  = rsqrtf(var + 1e-5f);
    float p0 = (y0 - mu) * rs * lg[i2 * DD + e0] + lb[i2 * DD + e0];
    float p1 = (y1 - mu) * rs * lg[i2 * DD + e1] + lb[i2 * DD + e1];
    g_P[base + e0] = fmaxf(p0, 0.0f);
    g_P[base + e1] = fmaxf(p1, 0.0f);
}

// ================= K2: HA = relu(P @ W1^T + b1) =================
__global__ void gemm_hidden_kernel(const float* __restrict__ W1, const float* __restrict__ b1)
{
    const int i  = blockIdx.y;
    const int b0 = (blockIdx.x & 7) * 8;
    const int n0 = (blockIdx.x >> 3) * 64;
    const int tid = threadIdx.x;
    const int tx = tid & 15, ty = tid >> 4;

    __shared__ __align__(16) float As[32][8];
    __shared__ __align__(16) float Bs[32][64];

    const float* Pb = g_P + (size_t)i * BB * DD;
    const float* Wb = W1 + (size_t)i * DQ * DD;

    float acc[4] = {};
    for (int k0 = 0; k0 < DD; k0 += 32) {
        if (tid < 64) {
            int r = tid >> 3, q = tid & 7;
            float4 v = *(const float4*)&Pb[(size_t)(b0 + r) * DD + k0 + q * 4];
            As[q*4+0][r] = v.x; As[q*4+1][r] = v.y; As[q*4+2][r] = v.z; As[q*4+3][r] = v.w;
        }
        #pragma unroll
        for (int q = 0; q < 4; ++q) {
            int idx = tid * 4 + q;
            int nr = idx >> 3, kq = idx & 7;
            float4 v = *(const float4*)&Wb[(size_t)(n0 + nr) * DD + k0 + kq * 4];
            Bs[kq*4+0][nr] = v.x; Bs[kq*4+1][nr] = v.y; Bs[kq*4+2][nr] = v.z; Bs[kq*4+3][nr] = v.w;
        }
        __syncthreads();
        #pragma unroll
        for (int k = 0; k < 32; ++k) {
            float a = As[k][ty];
            float4 w4 = *(const float4*)&Bs[k][tx * 4];
            acc[0] = fmaf(a, w4.x, acc[0]);
            acc[1] = fmaf(a, w4.y, acc[1]);
            acc[2] = fmaf(a, w4.z, acc[2]);
            acc[3] = fmaf(a, w4.w, acc[3]);
        }
        __syncthreads();
    }
    float4 o;
    o.x = fmaxf(acc[0] + b1[i*DQ + n0 + tx*4 + 0], 0.0f);
    o.y = fmaxf(acc[1] + b1[i*DQ + n0 + tx*4 + 1], 0.0f);
    o.z = fmaxf(acc[2] + b1[i*DQ + n0 + tx*4 + 2], 0.0f);
    o.w = fmaxf(acc[3] + b1[i*DQ + n0 + tx*4 + 3], 0.0f);
    *(float4*)&g_HA[((size_t)i * BB + b0 + ty) * DQ + n0 + tx * 4] = o;
}

// ================= K3: CW = HA @ W2^T + fused wf epilogue =================
__global__ void gemm_cw_wf_kernel(const float* __restrict__ W2,
                                  const float* __restrict__ b2v)
{
    const int i  = blockIdx.y;
    const int n0 = blockIdx.x * 32;
    const int tid = threadIdx.x;
    const int tx = tid & 7, ty = tid >> 3;

    __shared__ __align__(16) float As2[64][DQ];
    __shared__ __align__(16) float Bs[DQ][36];

    #pragma unroll
    for (int q = 0; q < 8; ++q) {
        int idx = tid + q * 256;
        int b = idx >> 5, kq = idx & 31;
        float4 v = *(const float4*)&g_HA[((size_t)i * BB + b) * DQ + kq * 4];
        *(float4*)&As2[b][kq * 4] = v;
    }
    #pragma unroll
    for (int q = 0; q < 4; ++q) {
        int idx = tid + q * 256;
        int nr = idx >> 5, kq = idx & 31;
        float4 v = *(const float4*)&W2[((size_t)i * DD + n0 + nr) * DQ + kq * 4];
        Bs[kq*4+0][nr] = v.x; Bs[kq*4+1][nr] = v.y; Bs[kq*4+2][nr] = v.z; Bs[kq*4+3][nr] = v.w;
    }
    __syncthreads();

    float acc[2][4] = {};
    #pragma unroll 8
    for (int k4 = 0; k4 < 32; ++k4) {
        float4 a0 = *(const float4*)&As2[ty][k4 * 4];
        float4 a1 = *(const float4*)&As2[ty + 32][k4 * 4];
        float av0[4] = {a0.x, a0.y, a0.z, a0.w};
        float av1[4] = {a1.x, a1.y, a1.z, a1.w};
        #pragma unroll
        for (int q = 0; q < 4; ++q) {
            float4 b4 = *(const float4*)&Bs[k4 * 4 + q][tx * 4];
            float bv[4] = {b4.x, b4.y, b4.z, b4.w};
            #pragma unroll
            for (int n2 = 0; n2 < 4; ++n2) {
                acc[0][n2] = fmaf(av0[q], bv[n2], acc[0][n2]);
                acc[1][n2] = fmaf(av1[q], bv[n2], acc[1][n2]);
            }
        }
    }

    #pragma unroll
    for (int rr = 0; rr < 2; ++rr) {
        int b = ty + rr * 32;
        int n = n0 + tx * 4;
        float4 p4 = *(const float4*)&g_P[((size_t)i * BB + b) * DD + n];
        float pv[4] = {p4.x, p4.y, p4.z, p4.w};
        float w[4], srow = 0.0f;
        #pragma unroll
        for (int q = 0; q < 4; ++q) {
            float pre = acc[rr][q] + b2v[i * DD + n + q];
            w[q] = pv[q] * sigm_(pre);
            srow += w[q];
            g_WFT[((size_t)i * DD + n + q) * BB + b] = w[q];
        }
        *(float4*)&g_WF[((size_t)i * BB + b) * DD + n] = make_float4(w[0], w[1], w[2], w[3]);
        #pragma unroll
        for (int off = 4; off; off >>= 1)
            srow += __shfl_xor_sync(FULLMASK, srow, off);
        if (tx == 0) atomicAdd(&g_S[i * BB + b], srow);
    }
}

// ================= K4: merged pairwise attention + combine =================
// Pass 0 uses the EXACT identity clamp(cur8,-cL8,cL8) == min(cur8, cL8)
// (cur8 >= 0 since wf >= 0), deleting one FMNMX per element.

template<int PASS>
__device__ __forceinline__ void run_pass(float4 (*sv)[8][128],
                                         float (*pw)[36],
                                         int j, int d, int lane, int warp, int bhalf,
                                         float a0, u64t (&hrp)[8],
                                         float cL, float isc, float g, float mb,
                                         float* __restrict__ accout)
{
    const int tid = warp * 32 + lane;
    const int bs = bhalf * 32;
    const float* wfj = g_WF + (size_t)j * BB * DD;
    const float isc8 = isc * 0.8f, isc2 = isc * 0.2f, cL8 = cL * 0.8f;

    u64t k02p, k08p, hnp[8];
    if (PASS == 1) {
        PK2(k02p, 0.2f, 0.2f);
        PK2(k08p, 0.8f, 0.8f);
        u64t kn1; PK2(kn1, -1.0f, -1.0f);
        #pragma unroll
        for (int q = 0; q < 8; ++q) MUL2(hnp[q], hrp[q], kn1);
    }

    #pragma unroll
    for (int q = 0; q < 4; ++q) {
        int idx = tid + q * 256;
        int rl = idx >> 7, col = idx & 127;
        int grow = (rl >> 2) * 32 + (rl & 3);
        sv[0][rl][col] = *(const float4*)&wfj[(size_t)grow * DD + col * 4];
    }
    __syncthreads();

    for (int c = 0; c < 8; ++c) {
        const int buf = c & 1;
        float4 nx[4];
        if (c < 7) {
            #pragma unroll
            for (int q = 0; q < 4; ++q) {
                int idx = tid + q * 256;
                int rl = idx >> 7, col = idx & 127;
                int grow = (rl >> 2) * 32 + (c + 1) * 4 + (rl & 3);
                nx[q] = *(const float4*)&wfj[(size_t)grow * DD + col * 4];
            }
        }
        #pragma unroll
        for (int bi = 0; bi < 4; ++bi) {
            const int bl = c * 4 + bi;
            float a  = __shfl_sync(FULLMASK, a0, bl);

            u64t sep, dotp;
            { float z = 0.0f; PK2(sep, z, z); PK2(dotp, z, z); }
            const float4* vr = sv[buf][bhalf * 4 + bi];

            if (PASS == 0) {
                u64t ap8p, ap2p;
                { float a8 = a * isc8, a2 = a * isc2; PK2(ap8p, a8, a8); PK2(ap2p, a2, a2); }
                #pragma unroll
                for (int k = 0; k < 4; ++k) {
                    float4 v = vr[k * 32 + lane];
                    u64t vp[2]; PK2(vp[0], v.x, v.y); PK2(vp[1], v.z, v.w);
                    #pragma unroll
                    for (int h2 = 0; h2 < 2; ++h2) {
                        u64t cur; MUL2(cur, ap8p, vp[h2]);
                        float c0, c1; UPK2(c0, c1, cur);
                        float m0 = fminf(c0, cL8);       // cur8 >= 0: one-sided clamp
                        float m1 = fminf(c1, cL8);
                        u64t mp; PK2(mp, m0, m1);
                        u64t f; FMA2(f, ap2p, vp[h2], mp);
                        ADD2(hrp[k*2+h2], hrp[k*2+h2], f);
                        float f0, f1; UPK2(f0, f1, f);
                        float e0 = ex2f_(f0), e1 = ex2f_(f1);
                        u64t ep; PK2(ep, e0, e1);
                        ADD2(sep, sep, ep);
                        FMA2(dotp, ep, vp[h2], dotp);
                    }
                }
            } else {
                u64t app;
                { float av = a * isc; PK2(app, av, av); }
                #pragma unroll
                for (int k = 0; k < 4; ++k) {
                    float4 v = vr[k * 32 + lane];
                    u64t vp[2]; PK2(vp[0], v.x, v.y); PK2(vp[1], v.z, v.w);
                    #pragma unroll
                    for (int h2 = 0; h2 < 2; ++h2) {
                        u64t u_; FMA2(u_, app, vp[h2], hnp[k*2+h2]);
                        float u0, u1; UPK2(u0, u1, u_);
                        float m0 = fminf(fmaxf(u0, -cL), cL);
                        float m1 = fminf(fmaxf(u1, -cL), cL);
                        u64t mp; PK2(mp, m0, m1);
                        u64t t; FMA2(t, k02p, u_, hrp[k*2+h2]);
                        u64t f; FMA2(f, k08p, mp, t);
                        float f0, f1; UPK2(f0, f1, f);
                        float e0 = ex2f_(f0), e1 = ex2f_(f1);
                        u64t ep; PK2(ep, e0, e1);
                        ADD2(sep, sep, ep);
                        FMA2(dotp, ep, vp[h2], dotp);
                    }
                }
            }
            float sl, sh, dl, dh;
            UPK2(sl, sh, sep); UPK2(dl, dh, dotp);
            pw[bi * 2 + 0][lane] = sl + sh;
            pw[bi * 2 + 1][lane] = dl + dh;
        }
        __syncwarp();
        if (lane < 8) {
            const float4* pr = (const float4*)pw[lane];
            float4 p0 = pr[0], p1 = pr[1], p2 = pr[2], p3 = pr[3];
            float4 p4 = pr[4], p5 = pr[5], p6 = pr[6], p7 = pr[7];
            p0.x += p1.x; p0.y += p1.y; p0.z += p1.z; p0.w += p1.w;
            p2.x += p3.x; p2.y += p3.y; p2.z += p3.z; p2.w += p3.w;
            p4.x += p5.x; p4.y += p5.y; p4.z += p5.z; p4.w += p5.w;
            p6.x += p7.x; p6.y += p7.y; p6.z += p7.z; p6.w += p7.w;
            p0.x += p2.x; p0.y += p2.y; p0.z += p2.z; p0.w += p2.w;
            p4.x += p6.x; p4.y += p6.y; p4.z += p6.z; p4.w += p6.w;
            float val = (p0.x + p4.x) + (p0.y + p4.y) + (p0.z + p4.z) + (p0.w + p4.w);
            float sev = __shfl_sync(0xFFu, val, lane & ~1);
            if (lane & 1) {
                int bl = c * 4 + (lane >> 1);
                float sj = __ldg(&g_S[j * BB + bs + bl]);
                accout[(size_t)(bs + bl) * DD + d] = g * (val * frcp_(sev) + mb * sj);
            }
        }
        if (c < 7) {
            #pragma unroll
            for (int q = 0; q < 4; ++q) {
                int idx = tid + q * 256;
                int rl = idx >> 7, col = idx & 127;
                sv[buf ^ 1][rl][col] = nx[q];
            }
        }
        __syncthreads();
    }
}

__global__ __launch_bounds__(256, 3) void attn_combine_kernel(
    const float* __restrict__ gamma,
    const float* __restrict__ mbias,
    const float* __restrict__ constraint,
    float* __restrict__ out, int out_size)
{
    __shared__ __align__(16) float4 sv[2][8][128];      // 32 KB staging
    __shared__ __align__(16) float s_part[8][8][36];    // 9 KB partials
    const int i     = blockIdx.y;
    const int warp  = threadIdx.x >> 5;
    const int lane  = threadIdx.x & 31;
    const int bhalf = warp & 1;
    const int d     = blockIdx.x * 4 + (warp >> 1);
    const int tid   = threadIdx.x;
    const int j1 = (i == 0) ? 1 : 0;
    const int j2 = (i == 2) ? 1 : 2;

    const float cL  = constraint[i] * L2E;
    const float isc = INV_SCALE * L2E;
    const float a0 = __ldg(&g_WFT[((size_t)i * DD + d) * BB + bhalf * 32 + lane]);

    u64t hrp[8];
    { float z = 0.0f; u64t zp; PK2(zp, z, z);
      #pragma unroll
      for (int q = 0; q < 8; ++q) hrp[q] = zp; }

    {
        const float g1 = sigm_(gamma[i * MM + j1]);
        const float m1 = mbias[i * MM + j1];
        run_pass<0>(sv, s_part[warp], j1, d, lane, warp, bhalf, a0, hrp, cL, isc, g1, m1,
                    g_A1 + (size_t)i * BB * DD);
    }

    // ---- exchange hr across the warp pair (reuse sv buffer) ----
    __syncthreads();
    u64t* hx = (u64t*)sv;
    #pragma unroll
    for (int k = 0; k < 4; ++k) {
        float4* dst = (float4*)&hx[warp * 256 + (k * 32 + lane) * 2];
        float h0, h1, h2, h3;
        UPK2(h0, h1, hrp[k*2+0]); UPK2(h2, h3, hrp[k*2+1]);
        *dst = make_float4(h0, h1, h2, h3);
    }
    __syncthreads();
    {
        const int p = warp ^ 1;
        u64t k320; PK2(k320, (1.0f/320.0f), (1.0f/320.0f));
        #pragma unroll
        for (int k = 0; k < 4; ++k) {
            float4 hp = *(const float4*)&hx[p * 256 + (k * 32 + lane) * 2];
            u64t hp0, hp1; PK2(hp0, hp.x, hp.y); PK2(hp1, hp.z, hp.w);
            u64t s0, s1;
            ADD2(s0, hrp[k*2+0], hp0);
            ADD2(s1, hrp[k*2+1], hp1);
            MUL2(hrp[k*2+0], s0, k320);
            MUL2(hrp[k*2+1], s1, k320);
        }
    }
    __syncthreads();

    {
        const float g2 = sigm_(gamma[i * MM + j2]);
        const float m2 = mbias[i * MM + j2];
        run_pass<1>(sv, s_part[warp], j2, d, lane, warp, bhalf, a0, hrp, cL, isc, g2, m2,
                    g_A2 + (size_t)i * BB * DD);
    }

    // ---- grid barrier over all 384 blocks (3/SM co-resident by launch_bounds) ----
    __threadfence();
    __syncthreads();
    if (tid == 0) {
        unsigned old = atomicAdd(&g_bar2, 1u);
        unsigned target = (old / K4_BLOCKS + 1u) * K4_BLOCKS;
        while ((int)(*(volatile unsigned*)&g_bar2 - target) < 0) {
            __nanosleep(32);
        }
    }
    __syncthreads();

    // ---- combine phase: mode-0 blocks write the output ----
    if (i == 0) {
        const int idx = blockIdx.x * 256 + tid;   // 0..32767
        const int NBD = BB * DD;
        float w = (g_WF[idx] + g_WF[NBD + idx] + g_WF[2*NBD + idx]) * (1.0f / 3.0f);
        float a = g_A1[idx] + g_A1[NBD + idx] + g_A1[2*NBD + idx]
                + g_A2[idx] + g_A2[NBD + idx] + g_A2[2*NBD + idx];
        out[idx] = w + a * (1.0f / 6.0f);

        if (blockIdx.x == 0 && tid < MM && out_size >= NBD + MM) {
            float sc[MM];
            #pragma unroll
            for (int ii = 0; ii < MM; ++ii) {
                int ja = (ii == 0) ? 1 : 0;
                int jb = (ii == 2) ? 1 : 2;
                sc[ii] = 0.5f * (sigm_(gamma[ii * MM + ja]) + sigm_(gamma[ii * MM + jb]));
            }
            float mx = fmaxf(sc[0], fmaxf(sc[1], sc[2]));
            float e0 = ex2f_((sc[0] - mx) * L2E);
            float e1 = ex2f_((sc[1] - mx) * L2E);
            float e2 = ex2f_((sc[2] - mx) * L2E);
            float inv = frcp_(e0 + e1 + e2);
            float ei = (tid == 0) ? e0 : ((tid == 1) ? e1 : e2);
            out[NBD + tid] = ei * inv;
        }
    }
}

// ================= launch =================
extern "C" void kernel_launch(void* const* d_in, const int* in_sizes, int n_in,
                              void* d_out, int out_size)
{
    const float* x      = (const float*)d_in[0];
    const float* proj_W = (const float*)d_in[1];
    const float* proj_b = (const float*)d_in[2];
    const float* ln_g   = (const float*)d_in[3];
    const float* ln_b   = (const float*)d_in[4];
    const float* imp_W1 = (const float*)d_in[5];
    const float* imp_b1 = (const float*)d_in[6];
    const float* imp_W2 = (const float*)d_in[7];
    const float* imp_b2 = (const float*)d_in[8];
    const float* gamma  = (const float*)d_in[9];
    const float* mbias  = (const float*)d_in[10];
    const float* constr = (const float*)d_in[11];
    float* out = (float*)d_out;

    // 1) y = x @ proj_W^T (split-K 8) + grid-sync + LN/ReLU
    k1_gemm1_ln<<<dim3(8, NSPL, MM), 256>>>(x, proj_W, proj_b, ln_g, ln_b);
    // 2) HA = relu(proj @ W1^T + b1)
    gemm_hidden_kernel<<<dim3(16, MM), 128>>>(imp_W1, imp_b1);
    // 3) CW = HA @ W2^T fused with wf epilogue
    gemm_cw_wf_kernel<<<dim3(16, MM), 256>>>(imp_W2, imp_b2);
    // 4) merged attention + grid barrier + combine (single wave, 3/SM)
    attn_combine_kernel<<<dim3(128, MM), 256>>>(gamma, mbias, constr, out, out_size);
}